// round 16
// baseline (speedup 1.0000x reference)
#include <cuda_runtime.h>
#include <cstdint>

// ---------------------------------------------------------------------------
// DeepGCN fused kernel, round 15 = R14 (validated: 3429us, rel_err 2.843e-6)
// + ONE minimal value-preserving diff: LN params (ln_g/ln_b) and b_rel are
// read directly from global (broadcast, L2-resident) instead of being staged
// into shared, deleting one __syncthreads per layer (20 barriers total).
//
//   Z = relu(LN(H));  P = Z @ [Wr | Wo]  (3 mma products: hh + hl + lh);
//   H += A @ P[:, :64] + P[:, 64:] + b_rel   (A exact in tf32, 2 products).
// ---------------------------------------------------------------------------

static constexpr int NUM_GRAPHS = 16384;
static constexpr int NG        = 23;
static constexpr int E_TOTAL   = 4194304;
static constexpr int HDIM      = 64;
static constexpr int NLAYERS   = 20;
static constexpr int NB        = 1024;
static constexpr int NT        = 16;
static constexpr int NC        = 3;
static constexpr int A_STRIDE  = NG * NG;    // 529

static constexpr int G    = 4;               // graphs per block
static constexpr int TPB  = 256;             // 8 warps
static constexpr int MROW = G * 24;          // 96 rows
static constexpr int LDH  = 68;              // H/Z stride  (conflict-free A-frag)
static constexpr int LDP  = 72;              // P stride    (conflict-free B-frag)
static constexpr int LDW  = 136;             // W stride    (conflict-free B-frag)
static constexpr int LDA  = 28;              // A-tile stride

// Shared layout (floats) — R14 layout (W double-buffered)
static constexpr int OFF_H   = 0;                          // [96][68]
static constexpr int OFF_ZH  = OFF_H  + MROW * LDH;        // [96][68]
static constexpr int OFF_ZL  = OFF_ZH + MROW * LDH;        // [96][68]
static constexpr int OFF_PQ  = OFF_ZL + MROW * LDH;        // [96][72]
static constexpr int OFF_PR  = OFF_PQ + MROW * LDP;        // [96][72]
static constexpr int OFF_W0  = OFF_PR + MROW * LDP;        // [64][136] raw fp32 buf0
static constexpr int OFF_W1  = OFF_W0 + 64 * LDW;          // [64][136] raw fp32 buf1
static constexpr int OFF_A   = OFF_W1 + 64 * LDW;          // [4][32][28]
static constexpr int OFF_BEN = OFF_A  + G * 32 * LDA;      // 64 (encoder bias)
static constexpr int SM_FLOATS = OFF_BEN + 64;             // 54464
static constexpr int SM_BYTES  = SM_FLOATS * 4;            // 217856 B (< 227KB)

// Device scratch (allocation-free rule: __device__ globals)
__device__ float g_A[(size_t)NUM_GRAPHS * A_STRIDE];
__device__ float g_pooled[(size_t)NUM_GRAPHS * HDIM];

// ---------------------------------------------------------------------------
__device__ __forceinline__ float tf32f(float x) {
    uint32_t y;
    asm("cvt.rna.tf32.f32 %0, %1;" : "=r"(y) : "f"(x));
    return __uint_as_float(y);
}

// D += A*B  (m16n8k8, tf32 inputs, fp32 accumulate)   [validated R8/R10/R14]
__device__ __forceinline__ void mma_tf32(float4& d,
                                         uint32_t a0, uint32_t a1,
                                         uint32_t a2, uint32_t a3,
                                         uint32_t b0, uint32_t b1) {
    asm volatile(
        "mma.sync.aligned.m16n8k8.row.col.f32.tf32.tf32.f32 "
        "{%0,%1,%2,%3}, {%4,%5,%6,%7}, {%8,%9}, {%0,%1,%2,%3};\n"
        : "+f"(d.x), "+f"(d.y), "+f"(d.z), "+f"(d.w)
        : "r"(a0), "r"(a1), "r"(a2), "r"(a3), "r"(b0), "r"(b1));
}

// A-fragment (16x8, row-major)   [validated mapping, R8/R10/R14]
__device__ __forceinline__ void ldA(const float* buf, int ld, int row0, int col0,
                                    int gr, int tg,
                                    uint32_t& a0, uint32_t& a1,
                                    uint32_t& a2, uint32_t& a3) {
    a0 = __float_as_uint(buf[(row0 + gr)     * ld + col0 + tg]);
    a1 = __float_as_uint(buf[(row0 + gr + 8) * ld + col0 + tg]);
    a2 = __float_as_uint(buf[(row0 + gr)     * ld + col0 + tg + 4]);
    a3 = __float_as_uint(buf[(row0 + gr + 8) * ld + col0 + tg + 4]);
}

// B-fragment (8x8) from fp32 buffer with ON-THE-FLY hi/lo tf32 split.
__device__ __forceinline__ void ldB_split(const float* buf, int ld, int k0, int n0,
                                          int gr, int tg,
                                          uint32_t& bh0, uint32_t& bh1,
                                          uint32_t& bl0, uint32_t& bl1) {
    float v0 = buf[(k0 + tg)     * ld + n0 + gr];
    float v1 = buf[(k0 + tg + 4) * ld + n0 + gr];
    float h0 = tf32f(v0), h1 = tf32f(v1);
    bh0 = __float_as_uint(h0);
    bh1 = __float_as_uint(h1);
    bl0 = __float_as_uint(tf32f(v0 - h0));
    bl1 = __float_as_uint(tf32f(v1 - h1));
}

// cp.async helpers (mechanism only; same bytes to same logical slots)
__device__ __forceinline__ void cp_async16(void* smem_dst, const void* gsrc) {
    uint32_t s = (uint32_t)__cvta_generic_to_shared(smem_dst);
    asm volatile("cp.async.cg.shared.global [%0], [%1], 16;\n"
                 :: "r"(s), "l"(gsrc) : "memory");
}
__device__ __forceinline__ void cp_commit() {
    asm volatile("cp.async.commit_group;\n" ::: "memory");
}
__device__ __forceinline__ void cp_wait1() {
    asm volatile("cp.async.wait_group 1;\n" ::: "memory");
}
__device__ __forceinline__ void cp_wait0() {
    asm volatile("cp.async.wait_group 0;\n" ::: "memory");
}

// ---------------------------------------------------------------------------
__global__ void zeroA_kernel() {
    const int n4 = NUM_GRAPHS * A_STRIDE / 4;
    float4* p = reinterpret_cast<float4*>(g_A);
    for (int i = blockIdx.x * blockDim.x + threadIdx.x; i < n4;
         i += gridDim.x * blockDim.x)
        p[i] = make_float4(0.f, 0.f, 0.f, 0.f);
}

__global__ void buildA_kernel(const int* __restrict__ ei) {
    int e = blockIdx.x * blockDim.x + threadIdx.x;
    if (e >= E_TOTAL) return;
    int s = ei[e];
    int d = ei[E_TOTAL + e];
    int g  = d / NG;
    int li = d - g * NG;
    int lj = s - g * NG;
    atomicAdd(&g_A[(size_t)g * A_STRIDE + li * NG + lj], 1.0f);
}

// ---------------------------------------------------------------------------
__global__ void __launch_bounds__(TPB, 1) gcn_main(
    const float* __restrict__ x,
    const float* __restrict__ W_enc, const float* __restrict__ b_enc,
    const float* __restrict__ ln_g,  const float* __restrict__ ln_b,
    const float* __restrict__ W_rel, const float* __restrict__ b_rel,
    const float* __restrict__ W_root)
{
    extern __shared__ float sm[];
    float* Hs  = sm + OFF_H;
    float* Zh  = sm + OFF_ZH;
    float* Zl  = sm + OFF_ZL;
    float* Pq  = sm + OFF_PQ;
    float* Pr  = sm + OFF_PR;
    float* As  = sm + OFF_A;
    float* ben = sm + OFF_BEN;
    float* Wenc_s = sm + OFF_W1;   // encoder weights parked in buf1 (layer 0
                                   // uses buf0; buf1 first overwritten at the
                                   // top of layer 0, after encoder reads)

    const int tid  = threadIdx.x;
    const int warp = tid >> 5;
    const int lane = tid & 31;
    const int gr   = lane >> 2;
    const int tg   = lane & 3;
    const int g0   = blockIdx.x * G;

    // ---- one-time staging: encoder W raw, A tiles; prefetch layer0 W ------
    for (int i = tid; i < 8 * HDIM; i += TPB)
        Wenc_s[(i >> 6) * LDW + (i & 63)] = W_enc[i];
    if (tid < HDIM) ben[tid] = b_enc[tid];
    for (int idx = tid; idx < G * 32 * LDA; idx += TPB) {
        int gl  = idx / (32 * LDA);
        int rem = idx - gl * (32 * LDA);
        int li  = rem / LDA;
        int lj  = rem - li * LDA;
        float v = 0.f;
        if (li < NG && lj < NG)
            v = g_A[(size_t)(g0 + gl) * A_STRIDE + li * NG + lj];
        As[idx] = v;     // small ints: exact in tf32 even as raw fp32 bits
    }
    {   // prefetch layer 0 weights into buf0
        const float4* Wr4 = reinterpret_cast<const float4*>(W_rel);
        const float4* Wo4 = reinterpret_cast<const float4*>(W_root);
        float* Wd = sm + OFF_W0;
        for (int i = tid; i < 1024; i += TPB) {
            int k  = i >> 4;
            int n4 = (i & 15) * 4;
            cp_async16(&Wd[k * LDW + n4],      Wr4 + i);
            cp_async16(&Wd[k * LDW + 64 + n4], Wo4 + i);
        }
        cp_commit();
    }
    __syncthreads();

    // ---- encoder: H = x @ W_enc + b_enc (fp32, one thread per row) --------
    if (tid < MROW) {
        int gl = tid / 24, node = tid - gl * 24;
        float* hr = Hs + tid * LDH;
        if (node < NG) {
            const float4* xr = reinterpret_cast<const float4*>(
                x + (size_t)((g0 + gl) * NG + node) * 8);
            float4 xa = xr[0], xb = xr[1];
            float xv[8] = {xa.x, xa.y, xa.z, xa.w, xb.x, xb.y, xb.z, xb.w};
            for (int n = 0; n < HDIM; n++) {
                float a = ben[n];
                #pragma unroll
                for (int k = 0; k < 8; k++) a = fmaf(xv[k], Wenc_s[k * LDW + n], a);
                hr[n] = a;
            }
        } else {
            for (int n = 0; n < HDIM; n++) hr[n] = 0.f;   // pad row
        }
    }

    // ---- layer loop --------------------------------------------------------
    for (int l = 0; l < NLAYERS; l++) {
        __syncthreads();   // Hs final; prior reads of Ws/Z/P complete

        // phase 1: issue cp.async prefetch of layer l+1 weights (alt buffer).
        // (LN params / b_rel are NOT staged — read from global below. This
        //  removes the barrier that used to follow this phase.)
        if (l + 1 < NLAYERS) {
            const int lp = l + 1;
            const float4* Wr4 = reinterpret_cast<const float4*>(W_rel  + lp * 4096);
            const float4* Wo4 = reinterpret_cast<const float4*>(W_root + lp * 4096);
            float* Wd = sm + ((lp & 1) ? OFF_W1 : OFF_W0);
            for (int i = tid; i < 1024; i += TPB) {
                int k  = i >> 4;
                int n4 = (i & 15) * 4;
                cp_async16(&Wd[k * LDW + n4],      Wr4 + i);
                cp_async16(&Wd[k * LDW + 64 + n4], Wo4 + i);
            }
            cp_commit();
        }

        // phase 2: Z = relu(LN(H)) split hi/lo (fp32 math, tid<96)
        // [same arithmetic as R14; LN params read directly from global]
        if (tid < MROW) {
            const float* lgp = ln_g + l * HDIM;
            const float* lbp = ln_b + l * HDIM;
            const float* hr = Hs + tid * LDH;
            float v[HDIM];
            float mu = 0.f;
            #pragma unroll
            for (int i = 0; i < 16; i++) {
                float4 t = *reinterpret_cast<const float4*>(hr + 4 * i);
                v[4*i] = t.x; v[4*i+1] = t.y; v[4*i+2] = t.z; v[4*i+3] = t.w;
                mu += t.x + t.y + t.z + t.w;
            }
            mu *= (1.f / HDIM);
            float var = 0.f;
            #pragma unroll
            for (int i = 0; i < HDIM; i++) {
                float d = v[i] - mu;
                var = fmaf(d, d, var);
            }
            float rs = rsqrtf(var * (1.f / HDIM) + 1e-5f);
            float* zh = Zh + tid * LDH;
            float* zl = Zl + tid * LDH;
            #pragma unroll
            for (int i = 0; i < HDIM; i++) {
                float z  = fmaxf(fmaf((v[i] - mu) * rs, lgp[i], lbp[i]), 0.f);
                float hi = tf32f(z);
                zh[i] = hi;
                zl[i] = tf32f(z - hi);
            }
        }
        // layer l's weights must be resident before GEMM1 reads them
        if (l + 1 < NLAYERS) cp_wait1(); else cp_wait0();
        __syncthreads();   // Z + W(buf l&1) ready

        const float* Ws = sm + ((l & 1) ? OFF_W1 : OFF_W0);

        // phase 3: GEMM1  P = Z @ [Wr|Wo]  (M=96, K=64, N=128)  [verbatim R14]
        // 8 warps, one (m48, n32) unit each: mhalf = warp>>2, nq = warp&3.
        {
            const int row0 = (warp >> 2) * 48;
            const int col0 = (warp & 3) * 32;
            float4 acc[3][4];
            #pragma unroll
            for (int mt = 0; mt < 3; mt++)
                #pragma unroll
                for (int nt = 0; nt < 4; nt++)
                    acc[mt][nt] = make_float4(0.f, 0.f, 0.f, 0.f);

            #pragma unroll
            for (int kt = 0; kt < 8; kt++) {
                uint32_t ah[3][4], al[3][4];
                #pragma unroll
                for (int mt = 0; mt < 3; mt++) {
                    ldA(Zh, LDH, row0 + mt * 16, kt * 8, gr, tg,
                        ah[mt][0], ah[mt][1], ah[mt][2], ah[mt][3]);
                    ldA(Zl, LDH, row0 + mt * 16, kt * 8, gr, tg,
                        al[mt][0], al[mt][1], al[mt][2], al[mt][3]);
                }
                #pragma unroll
                for (int nt = 0; nt < 4; nt++) {
                    uint32_t bh0, bh1, bl0, bl1;
                    ldB_split(Ws, LDW, kt * 8, col0 + nt * 8, gr, tg,
                              bh0, bh1, bl0, bl1);
                    #pragma unroll
                    for (int mt = 0; mt < 3; mt++) {
                        mma_tf32(acc[mt][nt], ah[mt][0], ah[mt][1], ah[mt][2], ah[mt][3], bh0, bh1);
                        mma_tf32(acc[mt][nt], ah[mt][0], ah[mt][1], ah[mt][2], ah[mt][3], bl0, bl1);
                        mma_tf32(acc[mt][nt], al[mt][0], al[mt][1], al[mt][2], al[mt][3], bh0, bh1);
                    }
                }
            }
            float* dst = (col0 < 64) ? Pq : Pr;
            const int cb = col0 & 63;
            #pragma unroll
            for (int mt = 0; mt < 3; mt++) {
                #pragma unroll
                for (int nt = 0; nt < 4; nt++) {
                    int r = row0 + mt * 16 + gr;
                    int c = cb + nt * 8 + 2 * tg;
                    *reinterpret_cast<float2*>(&dst[r * LDP + c]) =
                        make_float2(acc[mt][nt].x, acc[mt][nt].y);
                    *reinterpret_cast<float2*>(&dst[(r + 8) * LDP + c]) =
                        make_float2(acc[mt][nt].z, acc[mt][nt].w);
                }
            }
        }
        __syncthreads();   // Ps ready

        // phase 4: GEMM2  H += A @ Pq + Pr + b_rel   [verbatim R14; b_rel
        // read from global — same values]
        // 8 warps, one (m16, n64) job each: gj = warp>>1, mt = warp&1.
        {
            const float* brl = b_rel + l * HDIM;
            const int gj   = warp >> 1;
            const int mt   = warp & 1;
            const int rb   = gj * 24;
            const int row0 = rb + mt * 16;
            const float* Aw = As + gj * (32 * LDA);

            float4 acc[8];
            #pragma unroll
            for (int nt = 0; nt < 8; nt++) {
                int c = nt * 8 + 2 * tg;
                int ra = row0 + gr;
                acc[nt].x = Hs[ra * LDH + c]     + Pr[ra * LDP + c]     + brl[c];
                acc[nt].y = Hs[ra * LDH + c + 1] + Pr[ra * LDP + c + 1] + brl[c + 1];
                if (mt == 0) {
                    int rz = ra + 8;
                    acc[nt].z = Hs[rz * LDH + c]     + Pr[rz * LDP + c]     + brl[c];
                    acc[nt].w = Hs[rz * LDH + c + 1] + Pr[rz * LDP + c + 1] + brl[c + 1];
                } else {
                    acc[nt].z = 0.f;   // rows 24..31 = pad/next graph: not stored
                    acc[nt].w = 0.f;
                }
            }
            #pragma unroll
            for (int kt = 0; kt < 3; kt++) {
                uint32_t a0, a1, a2, a3;     // raw fp32 ints == exact tf32
                ldA(Aw, LDA, mt * 16, kt * 8, gr, tg, a0, a1, a2, a3);
                #pragma unroll
                for (int nt = 0; nt < 8; nt++) {
                    uint32_t bh0, bh1, bl0, bl1;
                    ldB_split(Pq, LDP, rb + kt * 8, nt * 8, gr, tg,
                              bh0, bh1, bl0, bl1);
                    mma_tf32(acc[nt], a0, a1, a2, a3, bh0, bh1);
                    mma_tf32(acc[nt], a0, a1, a2, a3, bl0, bl1);
                }
            }
            #pragma unroll
            for (int nt = 0; nt < 8; nt++) {
                int c = nt * 8 + 2 * tg;
                int ra = row0 + gr;
                *reinterpret_cast<float2*>(&Hs[ra * LDH + c]) =
                    make_float2(acc[nt].x, acc[nt].y);
                if (mt == 0) {
                    *reinterpret_cast<float2*>(&Hs[(ra + 8) * LDH + c]) =
                        make_float2(acc[nt].z, acc[nt].w);
                }
            }
        }
    }

    // ---- per-graph mean pool (exclude pad rows) ----------------------------
    __syncthreads();
    {
        int gl = tid >> 6;
        int f  = tid & 63;
        const float* hb = Hs + (gl * 24) * LDH + f;
        float s = 0.f;
        #pragma unroll
        for (int i = 0; i < NG; i++) s += hb[i * LDH];
        g_pooled[(size_t)(g0 + gl) * HDIM + f] = s * (1.f / NG);
    }
}

// ---------------------------------------------------------------------------
__global__ void head_kernel(const float* __restrict__ pos,
                            const float* __restrict__ W1, const float* __restrict__ b1,
                            const float* __restrict__ W2, const float* __restrict__ b2,
                            float* __restrict__ out)
{
    __shared__ float vs[HDIM];
    __shared__ float h1s[HDIM];
    const int b = blockIdx.x;
    const int f = threadIdx.x;

    float v = 0.f;
    #pragma unroll
    for (int tt = 0; tt < NT; tt++)
        v += g_pooled[(size_t)(b * NT + tt) * HDIM + f] + pos[tt * HDIM + f];
    vs[f] = v * (1.f / NT);
    __syncthreads();

    float acc = b1[f];
    #pragma unroll
    for (int k = 0; k < HDIM; k++) acc = fmaf(vs[k], W1[k * HDIM + f], acc);
    h1s[f] = fmaxf(acc, 0.f);
    __syncthreads();

    if (f < NC) {
        float o = b2[f];
        #pragma unroll
        for (int k = 0; k < HDIM; k++) o = fmaf(h1s[k], W2[k * NC + f], o);
        out[b * NC + f] = o;
    }
}

// ---------------------------------------------------------------------------
extern "C" void kernel_launch(void* const* d_in, const int* in_sizes, int n_in,
                              void* d_out, int out_size)
{
    const float* x     = (const float*)d_in[0];
    const int*   ei    = (const int*)  d_in[1];
    // d_in[2] = batch (unused: graphs are contiguous blocks of 23 nodes)
    const float* W_enc = (const float*)d_in[3];
    const float* b_enc = (const float*)d_in[4];
    const float* ln_g  = (const float*)d_in[5];
    const float* ln_b  = (const float*)d_in[6];
    const float* W_rel = (const float*)d_in[7];
    const float* b_rel = (const float*)d_in[8];
    const float* W_root= (const float*)d_in[9];
    const float* pos   = (const float*)d_in[10];
    const float* W1    = (const float*)d_in[11];
    const float* b1    = (const float*)d_in[12];
    const float* W2    = (const float*)d_in[13];
    const float* b2    = (const float*)d_in[14];
    float* out = (float*)d_out;

    (void)in_sizes; (void)n_in; (void)out_size;

    cudaFuncSetAttribute(gcn_main, cudaFuncAttributeMaxDynamicSharedMemorySize,
                         SM_BYTES);

    zeroA_kernel<<<1024, 256>>>();
    buildA_kernel<<<(E_TOTAL + 255) / 256, 256>>>(ei);
    gcn_main<<<NUM_GRAPHS / G, TPB, SM_BYTES>>>(
        x, W_enc, b_enc, ln_g, ln_b, W_rel, b_rel, W_root);
    head_kernel<<<NB, HDIM>>>(pos, W1, b1, W2, b2, out);
}

// round 17
// speedup vs baseline: 1.0631x; 1.0631x over previous
#include <cuda_runtime.h>
#include <cstdint>

// ---------------------------------------------------------------------------
// DeepGCN fused kernel, round 16 = R15 (validated: 3429/3436us, 2.843e-6)
// with G=2 graphs/block so TWO blocks co-reside per SM (16 warps/SM) and
// phase-latency of one block hides under the other's compute.
//
// Enumerated diffs from R15 (everything else verbatim):
//  1. G 4->2 (MROW 48), grid 8192.
//  2. Single W buffer (prefetch for l+1 issued AFTER GEMM1's last Ws read,
//     overlapping GEMM2 + next LN); encoder W in a small dense array.
//  3. GEMM1: 8 warps x (m48,n16) strips (col0 = warp*16) -- partitioning
//     only; per-output accumulation order identical.
//  4. GEMM2: R15-verbatim body behind `if (warp < 4)`.
//  5. Pool guarded to tid < G*HDIM.
// smem 108.5KB/block -> 2 blocks/SM. __launch_bounds__(256, 2).
// ---------------------------------------------------------------------------

static constexpr int NUM_GRAPHS = 16384;
static constexpr int NG        = 23;
static constexpr int E_TOTAL   = 4194304;
static constexpr int HDIM      = 64;
static constexpr int NLAYERS   = 20;
static constexpr int NB        = 1024;
static constexpr int NT        = 16;
static constexpr int NC        = 3;
static constexpr int A_STRIDE  = NG * NG;    // 529

static constexpr int G    = 2;               // graphs per block
static constexpr int TPB  = 256;             // 8 warps
static constexpr int MROW = G * 24;          // 48 rows (23 nodes + 1 pad each)
static constexpr int LDH  = 68;              // H/Z stride  (conflict-free A-frag)
static constexpr int LDP  = 72;              // P stride    (conflict-free B-frag)
static constexpr int LDW  = 136;             // W stride    (conflict-free B-frag)
static constexpr int LDA  = 28;              // A-tile stride

// Shared layout (floats)
static constexpr int OFF_H    = 0;                         // [48][68]
static constexpr int OFF_ZH   = OFF_H  + MROW * LDH;       // [48][68]
static constexpr int OFF_ZL   = OFF_ZH + MROW * LDH;       // [48][68]
static constexpr int OFF_PQ   = OFF_ZL + MROW * LDH;       // [48][72]
static constexpr int OFF_PR   = OFF_PQ + MROW * LDP;       // [48][72]
static constexpr int OFF_W    = OFF_PR + MROW * LDP;       // [64][136] raw fp32
static constexpr int OFF_A    = OFF_W  + 64 * LDW;         // [2][32][28]
static constexpr int OFF_WENC = OFF_A  + G * 32 * LDA;     // [8][64] dense
static constexpr int OFF_BEN  = OFF_WENC + 8 * HDIM;       // 64
static constexpr int SM_FLOATS = OFF_BEN + 64;             // 27776
static constexpr int SM_BYTES  = SM_FLOATS * 4;            // 111104 B -> 2/SM

// Device scratch (allocation-free rule: __device__ globals)
__device__ float g_A[(size_t)NUM_GRAPHS * A_STRIDE];
__device__ float g_pooled[(size_t)NUM_GRAPHS * HDIM];

// ---------------------------------------------------------------------------
__device__ __forceinline__ float tf32f(float x) {
    uint32_t y;
    asm("cvt.rna.tf32.f32 %0, %1;" : "=r"(y) : "f"(x));
    return __uint_as_float(y);
}

// D += A*B  (m16n8k8, tf32 inputs, fp32 accumulate)   [validated R8/R10/R14]
__device__ __forceinline__ void mma_tf32(float4& d,
                                         uint32_t a0, uint32_t a1,
                                         uint32_t a2, uint32_t a3,
                                         uint32_t b0, uint32_t b1) {
    asm volatile(
        "mma.sync.aligned.m16n8k8.row.col.f32.tf32.tf32.f32 "
        "{%0,%1,%2,%3}, {%4,%5,%6,%7}, {%8,%9}, {%0,%1,%2,%3};\n"
        : "+f"(d.x), "+f"(d.y), "+f"(d.z), "+f"(d.w)
        : "r"(a0), "r"(a1), "r"(a2), "r"(a3), "r"(b0), "r"(b1));
}

// A-fragment (16x8, row-major)   [validated mapping, R8/R10/R14]
__device__ __forceinline__ void ldA(const float* buf, int ld, int row0, int col0,
                                    int gr, int tg,
                                    uint32_t& a0, uint32_t& a1,
                                    uint32_t& a2, uint32_t& a3) {
    a0 = __float_as_uint(buf[(row0 + gr)     * ld + col0 + tg]);
    a1 = __float_as_uint(buf[(row0 + gr + 8) * ld + col0 + tg]);
    a2 = __float_as_uint(buf[(row0 + gr)     * ld + col0 + tg + 4]);
    a3 = __float_as_uint(buf[(row0 + gr + 8) * ld + col0 + tg + 4]);
}

// B-fragment (8x8) from fp32 buffer with ON-THE-FLY hi/lo tf32 split.
__device__ __forceinline__ void ldB_split(const float* buf, int ld, int k0, int n0,
                                          int gr, int tg,
                                          uint32_t& bh0, uint32_t& bh1,
                                          uint32_t& bl0, uint32_t& bl1) {
    float v0 = buf[(k0 + tg)     * ld + n0 + gr];
    float v1 = buf[(k0 + tg + 4) * ld + n0 + gr];
    float h0 = tf32f(v0), h1 = tf32f(v1);
    bh0 = __float_as_uint(h0);
    bh1 = __float_as_uint(h1);
    bl0 = __float_as_uint(tf32f(v0 - h0));
    bl1 = __float_as_uint(tf32f(v1 - h1));
}

// cp.async helpers (mechanism only; same bytes to same logical slots)
__device__ __forceinline__ void cp_async16(void* smem_dst, const void* gsrc) {
    uint32_t s = (uint32_t)__cvta_generic_to_shared(smem_dst);
    asm volatile("cp.async.cg.shared.global [%0], [%1], 16;\n"
                 :: "r"(s), "l"(gsrc) : "memory");
}
__device__ __forceinline__ void cp_commit() {
    asm volatile("cp.async.commit_group;\n" ::: "memory");
}
__device__ __forceinline__ void cp_wait0() {
    asm volatile("cp.async.wait_group 0;\n" ::: "memory");
}

// ---------------------------------------------------------------------------
__global__ void zeroA_kernel() {
    const int n4 = NUM_GRAPHS * A_STRIDE / 4;
    float4* p = reinterpret_cast<float4*>(g_A);
    for (int i = blockIdx.x * blockDim.x + threadIdx.x; i < n4;
         i += gridDim.x * blockDim.x)
        p[i] = make_float4(0.f, 0.f, 0.f, 0.f);
}

__global__ void buildA_kernel(const int* __restrict__ ei) {
    int e = blockIdx.x * blockDim.x + threadIdx.x;
    if (e >= E_TOTAL) return;
    int s = ei[e];
    int d = ei[E_TOTAL + e];
    int g  = d / NG;
    int li = d - g * NG;
    int lj = s - g * NG;
    atomicAdd(&g_A[(size_t)g * A_STRIDE + li * NG + lj], 1.0f);
}

// ---------------------------------------------------------------------------
__global__ void __launch_bounds__(TPB, 2) gcn_main(
    const float* __restrict__ x,
    const float* __restrict__ W_enc, const float* __restrict__ b_enc,
    const float* __restrict__ ln_g,  const float* __restrict__ ln_b,
    const float* __restrict__ W_rel, const float* __restrict__ b_rel,
    const float* __restrict__ W_root)
{
    extern __shared__ float sm[];
    float* Hs  = sm + OFF_H;
    float* Zh  = sm + OFF_ZH;
    float* Zl  = sm + OFF_ZL;
    float* Pq  = sm + OFF_PQ;
    float* Pr  = sm + OFF_PR;
    float* Ws  = sm + OFF_W;
    float* As  = sm + OFF_A;
    float* wenc = sm + OFF_WENC;
    float* ben  = sm + OFF_BEN;

    const int tid  = threadIdx.x;
    const int warp = tid >> 5;
    const int lane = tid & 31;
    const int gr   = lane >> 2;
    const int tg   = lane & 3;
    const int g0   = blockIdx.x * G;

    // ---- one-time staging: encoder W (dense), A tiles; prefetch layer0 W --
    for (int i = tid; i < 8 * HDIM; i += TPB) wenc[i] = W_enc[i];
    if (tid < HDIM) ben[tid] = b_enc[tid];
    for (int idx = tid; idx < G * 32 * LDA; idx += TPB) {
        int gl  = idx / (32 * LDA);
        int rem = idx - gl * (32 * LDA);
        int li  = rem / LDA;
        int lj  = rem - li * LDA;
        float v = 0.f;
        if (li < NG && lj < NG)
            v = g_A[(size_t)(g0 + gl) * A_STRIDE + li * NG + lj];
        As[idx] = v;     // small ints: exact in tf32 even as raw fp32 bits
    }
    {   // prefetch layer 0 weights into Ws
        const float4* Wr4 = reinterpret_cast<const float4*>(W_rel);
        const float4* Wo4 = reinterpret_cast<const float4*>(W_root);
        for (int i = tid; i < 1024; i += TPB) {
            int k  = i >> 4;
            int n4 = (i & 15) * 4;
            cp_async16(&Ws[k * LDW + n4],      Wr4 + i);
            cp_async16(&Ws[k * LDW + 64 + n4], Wo4 + i);
        }
        cp_commit();
    }
    __syncthreads();

    // ---- encoder: H = x @ W_enc + b_enc (fp32, one thread per row) --------
    if (tid < MROW) {
        int gl = tid / 24, node = tid - gl * 24;
        float* hr = Hs + tid * LDH;
        if (node < NG) {
            const float4* xr = reinterpret_cast<const float4*>(
                x + (size_t)((g0 + gl) * NG + node) * 8);
            float4 xa = xr[0], xb = xr[1];
            float xv[8] = {xa.x, xa.y, xa.z, xa.w, xb.x, xb.y, xb.z, xb.w};
            for (int n = 0; n < HDIM; n++) {
                float a = ben[n];
                #pragma unroll
                for (int k = 0; k < 8; k++) a = fmaf(xv[k], wenc[k * HDIM + n], a);
                hr[n] = a;
            }
        } else {
            for (int n = 0; n < HDIM; n++) hr[n] = 0.f;   // pad row
        }
    }

    // ---- layer loop --------------------------------------------------------
    for (int l = 0; l < NLAYERS; l++) {
        __syncthreads();   // Hs final; prior reads of Z/P complete

        // phase 1: Z = relu(LN(H)) split hi/lo (fp32 math, tid<48)
        // [verbatim R15; LN params read directly from global]
        if (tid < MROW) {
            const float* lgp = ln_g + l * HDIM;
            const float* lbp = ln_b + l * HDIM;
            const float* hr = Hs + tid * LDH;
            float v[HDIM];
            float mu = 0.f;
            #pragma unroll
            for (int i = 0; i < 16; i++) {
                float4 t = *reinterpret_cast<const float4*>(hr + 4 * i);
                v[4*i] = t.x; v[4*i+1] = t.y; v[4*i+2] = t.z; v[4*i+3] = t.w;
                mu += t.x + t.y + t.z + t.w;
            }
            mu *= (1.f / HDIM);
            float var = 0.f;
            #pragma unroll
            for (int i = 0; i < HDIM; i++) {
                float d = v[i] - mu;
                var = fmaf(d, d, var);
            }
            float rs = rsqrtf(var * (1.f / HDIM) + 1e-5f);
            float* zh = Zh + tid * LDH;
            float* zl = Zl + tid * LDH;
            #pragma unroll
            for (int i = 0; i < HDIM; i++) {
                float z  = fmaxf(fmaf((v[i] - mu) * rs, lgp[i], lbp[i]), 0.f);
                float hi = tf32f(z);
                zh[i] = hi;
                zl[i] = tf32f(z - hi);
            }
        }
        // layer l's weights (prefetched last iteration / pre-loop) must land
        cp_wait0();
        __syncthreads();   // Z + Ws ready

        // phase 2: GEMM1  P = Z @ [Wr|Wo]  (M=48, K=64, N=128)
        // 8 warps, one (m48, n16) strip each: col0 = warp*16.
        // Per-output accumulation order identical to R15 (kt; hh,hl,lh).
        {
            const int col0 = warp * 16;
            float4 acc[3][2];
            #pragma unroll
            for (int mt = 0; mt < 3; mt++)
                #pragma unroll
                for (int nt = 0; nt < 2; nt++)
                    acc[mt][nt] = make_float4(0.f, 0.f, 0.f, 0.f);

            #pragma unroll
            for (int kt = 0; kt < 8; kt++) {
                uint32_t ah[3][4], al[3][4];
                #pragma unroll
                for (int mt = 0; mt < 3; mt++) {
                    ldA(Zh, LDH, mt * 16, kt * 8, gr, tg,
                        ah[mt][0], ah[mt][1], ah[mt][2], ah[mt][3]);
                    ldA(Zl, LDH, mt * 16, kt * 8, gr, tg,
                        al[mt][0], al[mt][1], al[mt][2], al[mt][3]);
                }
                #pragma unroll
                for (int nt = 0; nt < 2; nt++) {
                    uint32_t bh0, bh1, bl0, bl1;
                    ldB_split(Ws, LDW, kt * 8, col0 + nt * 8, gr, tg,
                              bh0, bh1, bl0, bl1);
                    #pragma unroll
                    for (int mt = 0; mt < 3; mt++) {
                        mma_tf32(acc[mt][nt], ah[mt][0], ah[mt][1], ah[mt][2], ah[mt][3], bh0, bh1);
                        mma_tf32(acc[mt][nt], ah[mt][0], ah[mt][1], ah[mt][2], ah[mt][3], bl0, bl1);
                        mma_tf32(acc[mt][nt], al[mt][0], al[mt][1], al[mt][2], al[mt][3], bh0, bh1);
                    }
                }
            }
            float* dst = (col0 < 64) ? Pq : Pr;
            const int cb = col0 & 63;
            #pragma unroll
            for (int mt = 0; mt < 3; mt++) {
                #pragma unroll
                for (int nt = 0; nt < 2; nt++) {
                    int r = mt * 16 + gr;
                    int c = cb + nt * 8 + 2 * tg;
                    *reinterpret_cast<float2*>(&dst[r * LDP + c]) =
                        make_float2(acc[mt][nt].x, acc[mt][nt].y);
                    *reinterpret_cast<float2*>(&dst[(r + 8) * LDP + c]) =
                        make_float2(acc[mt][nt].z, acc[mt][nt].w);
                }
            }
        }
        __syncthreads();   // Ps ready; ALL Ws reads of layer l done

        // phase 3: issue cp.async prefetch of layer l+1 weights into Ws
        // (safe: all reads complete; overlaps GEMM2 + next LN)
        if (l + 1 < NLAYERS) {
            const int lp = l + 1;
            const float4* Wr4 = reinterpret_cast<const float4*>(W_rel  + lp * 4096);
            const float4* Wo4 = reinterpret_cast<const float4*>(W_root + lp * 4096);
            for (int i = tid; i < 1024; i += TPB) {
                int k  = i >> 4;
                int n4 = (i & 15) * 4;
                cp_async16(&Ws[k * LDW + n4],      Wr4 + i);
                cp_async16(&Ws[k * LDW + 64 + n4], Wo4 + i);
            }
            cp_commit();
        }

        // phase 4: GEMM2  H += A @ Pq + Pr + b_rel   [verbatim R15 body,
        // guarded to warps 0..3 (G=2 -> 4 jobs of (m16, n64))]
        if (warp < 2 * G) {
            const float* brl = b_rel + l * HDIM;
            const int gj   = warp >> 1;
            const int mt   = warp & 1;
            const int rb   = gj * 24;
            const int row0 = rb + mt * 16;
            const float* Aw = As + gj * (32 * LDA);

            float4 acc[8];
            #pragma unroll
            for (int nt = 0; nt < 8; nt++) {
                int c = nt * 8 + 2 * tg;
                int ra = row0 + gr;
                acc[nt].x = Hs[ra * LDH + c]     + Pr[ra * LDP + c]     + brl[c];
                acc[nt].y = Hs[ra * LDH + c + 1] + Pr[ra * LDP + c + 1] + brl[c + 1];
                if (mt == 0) {
                    int rz = ra + 8;
                    acc[nt].z = Hs[rz * LDH + c]     + Pr[rz * LDP + c]     + brl[c];
                    acc[nt].w = Hs[rz * LDH + c + 1] + Pr[rz * LDP + c + 1] + brl[c + 1];
                } else {
                    acc[nt].z = 0.f;   // rows 24..31 = pad/next graph: not stored
                    acc[nt].w = 0.f;
                }
            }
            #pragma unroll
            for (int kt = 0; kt < 3; kt++) {
                uint32_t a0, a1, a2, a3;     // raw fp32 ints == exact tf32
                ldA(Aw, LDA, mt * 16, kt * 8, gr, tg, a0, a1, a2, a3);
                #pragma unroll
                for (int nt = 0; nt < 8; nt++) {
                    uint32_t bh0, bh1, bl0, bl1;
                    ldB_split(Pq, LDP, rb + kt * 8, nt * 8, gr, tg,
                              bh0, bh1, bl0, bl1);
                    mma_tf32(acc[nt], a0, a1, a2, a3, bh0, bh1);
                    mma_tf32(acc[nt], a0, a1, a2, a3, bl0, bl1);
                }
            }
            #pragma unroll
            for (int nt = 0; nt < 8; nt++) {
                int c = nt * 8 + 2 * tg;
                int ra = row0 + gr;
                *reinterpret_cast<float2*>(&Hs[ra * LDH + c]) =
                    make_float2(acc[nt].x, acc[nt].y);
                if (mt == 0) {
                    *reinterpret_cast<float2*>(&Hs[(ra + 8) * LDH + c]) =
                        make_float2(acc[nt].z, acc[nt].w);
                }
            }
        }
    }

    // ---- per-graph mean pool (exclude pad rows) ----------------------------
    __syncthreads();
    if (tid < G * HDIM) {
        int gl = tid >> 6;
        int f  = tid & 63;
        const float* hb = Hs + (gl * 24) * LDH + f;
        float s = 0.f;
        #pragma unroll
        for (int i = 0; i < NG; i++) s += hb[i * LDH];
        g_pooled[(size_t)(g0 + gl) * HDIM + f] = s * (1.f / NG);
    }
}

// ---------------------------------------------------------------------------
__global__ void head_kernel(const float* __restrict__ pos,
                            const float* __restrict__ W1, const float* __restrict__ b1,
                            const float* __restrict__ W2, const float* __restrict__ b2,
                            float* __restrict__ out)
{
    __shared__ float vs[HDIM];
    __shared__ float h1s[HDIM];
    const int b = blockIdx.x;
    const int f = threadIdx.x;

    float v = 0.f;
    #pragma unroll
    for (int tt = 0; tt < NT; tt++)
        v += g_pooled[(size_t)(b * NT + tt) * HDIM + f] + pos[tt * HDIM + f];
    vs[f] = v * (1.f / NT);
    __syncthreads();

    float acc = b1[f];
    #pragma unroll
    for (int k = 0; k < HDIM; k++) acc = fmaf(vs[k], W1[k * HDIM + f], acc);
    h1s[f] = fmaxf(acc, 0.f);
    __syncthreads();

    if (f < NC) {
        float o = b2[f];
        #pragma unroll
        for (int k = 0; k < HDIM; k++) o = fmaf(h1s[k], W2[k * NC + f], o);
        out[b * NC + f] = o;
    }
}

// ---------------------------------------------------------------------------
extern "C" void kernel_launch(void* const* d_in, const int* in_sizes, int n_in,
                              void* d_out, int out_size)
{
    const float* x     = (const float*)d_in[0];
    const int*   ei    = (const int*)  d_in[1];
    // d_in[2] = batch (unused: graphs are contiguous blocks of 23 nodes)
    const float* W_enc = (const float*)d_in[3];
    const float* b_enc = (const float*)d_in[4];
    const float* ln_g  = (const float*)d_in[5];
    const float* ln_b  = (const float*)d_in[6];
    const float* W_rel = (const float*)d_in[7];
    const float* b_rel = (const float*)d_in[8];
    const float* W_root= (const float*)d_in[9];
    const float* pos   = (const float*)d_in[10];
    const float* W1    = (const float*)d_in[11];
    const float* b1    = (const float*)d_in[12];
    const float* W2    = (const float*)d_in[13];
    const float* b2    = (const float*)d_in[14];
    float* out = (float*)d_out;

    (void)in_sizes; (void)n_in; (void)out_size;

    cudaFuncSetAttribute(gcn_main, cudaFuncAttributeMaxDynamicSharedMemorySize,
                         SM_BYTES);

    zeroA_kernel<<<1024, 256>>>();
    buildA_kernel<<<(E_TOTAL + 255) / 256, 256>>>(ei);
    gcn_main<<<NUM_GRAPHS / G, TPB, SM_BYTES>>>(
        x, W_enc, b_enc, ln_g, ln_b, W_rel, b_rel, W_root);
    head_kernel<<<NB, HDIM>>>(pos, W1, b1, W2, b2, out);
}